// round 14
// baseline (speedup 1.0000x reference)
#include <cuda_runtime.h>
#include <cuda_bf16.h>
#include <math.h>

// Problem constants
#define BB   16
#define CIN  256
#define COUT 128
#define HH   32
#define WW   32
#define HW   1024          // 32*32
#define KK9  9
#define KDEF 2304          // 9*256  (deform GEMM K)
#define KUP  512           // 128*4  (deconv GEMM K per parity)
#define N1TOT 16384        // B*HW   (BN1 population)
#define N2TOT 65536        // B*4*HW (BN2 population)

// ---------------- scratch (device globals; no allocation) ----------------
__device__ float g_off_part[4 * 16 * 27 * 1024];          // cin-group partials
__device__ float g_off[16 * 27 * 1024];                   // offsets (raw) + mask (sigmoid)
__device__ float g_samp[16 * 9 * 256 * 1024];             // sampled B matrix (151 MB)
__device__ float g_wdefT[2304 * 128];                     // deform weights, [kc][o]
__device__ float g_wupT[4 * 512 * 128];                   // deconv sub-kernels, [par][kc][o]
__device__ float g_y[16 * 128 * 1024];                    // deform out (pre-BN)
__device__ float g_y2[16 * 128 * 1024];                   // post BN+ReLU
__device__ float g_z[16 * 4 * 128 * 1024];                // deconv out, parity-blocked (pre-BN)
__device__ float g_part1[128 * 128 * 2];                  // BN1 per-block partials
__device__ float g_part2[512 * 128 * 2];                  // BN2 per-block partials
__device__ float g_scale1[128], g_shift1[128];
__device__ float g_scale2[128], g_shift2[128];

// ---------------- K1: offset conv 3x3 (256 -> 27), cin split 4 ways ------
__global__ __launch_bounds__(256) void k_offconv(const float* __restrict__ x,
                                                 const float* __restrict__ w_off) {
    const int tile = blockIdx.x;      // 0..3  (8 rows each)
    const int b    = blockIdx.y;      // 0..15
    const int grp  = blockIdx.z;      // 0..3  (64 cin each)
    const int h0   = tile * 8;
    const int c0b  = grp * 64;

    __shared__ float xs[4][10][36];
    __shared__ float ws[4][9][28];

    const int t   = threadIdx.x;
    const int tx  = t & 31;
    const int tyy = t >> 5;

    float acc[27];
#pragma unroll
    for (int i = 0; i < 27; i++) acc[i] = 0.f;

    for (int cc = 0; cc < 64; cc += 4) {
        // stage x patch: 4 cin x 10 rows x 34 cols (zero padded)
        for (int e = t; e < 4 * 10 * 34; e += 256) {
            int ci = e / 340, rem = e % 340;
            int r = rem / 34, col = rem % 34;
            int gh = h0 - 1 + r, gw = col - 1;
            float v = 0.f;
            if (gh >= 0 && gh < HH && gw >= 0 && gw < WW)
                v = x[(((size_t)b * CIN + c0b + cc + ci) << 10) + gh * WW + gw];
            xs[ci][r][col] = v;
        }
        // stage weights: [ci][tap][c27]
        for (int e = t; e < 4 * 9 * 27; e += 256) {
            int ci = e / 243, rem = e % 243;
            int tap = rem / 27, c27 = rem % 27;
            ws[ci][tap][c27] = w_off[((size_t)c27 * CIN + c0b + cc + ci) * 9 + tap];
        }
        __syncthreads();
#pragma unroll
        for (int ci = 0; ci < 4; ci++) {
#pragma unroll
            for (int tap = 0; tap < 9; tap++) {
                float xv = xs[ci][tyy + tap / 3][tx + tap % 3];
#pragma unroll
                for (int c27 = 0; c27 < 27; c27++)
                    acc[c27] = fmaf(xv, ws[ci][tap][c27], acc[c27]);
            }
        }
        __syncthreads();
    }

    float* op = g_off_part + (size_t)grp * (16 * 27 * 1024) +
                ((size_t)b * 27) * 1024 + (h0 + tyy) * WW + tx;
#pragma unroll
    for (int c27 = 0; c27 < 27; c27++) op[(size_t)c27 << 10] = acc[c27];
}

// K1b: reduce partials + bias; sigmoid on mask channels (18..26)
__global__ void k_offred(const float* __restrict__ b_off) {
    int idx = blockIdx.x * 256 + threadIdx.x;
    if (idx >= 16 * 27 * 1024) return;
    int c27 = (idx >> 10) % 27;
    float v = b_off[c27];
#pragma unroll
    for (int g = 0; g < 4; g++) v += g_off_part[(size_t)g * (16 * 27 * 1024) + idx];
    if (c27 >= 18) v = 1.f / (1.f + expf(-v));
    g_off[idx] = v;
}

// ---------------- weight prepack ----------------
__global__ void k_prep_wdefT(const float* __restrict__ w_dcn) {
    int idx = blockIdx.x * 256 + threadIdx.x;
    if (idx >= 2304 * 128) return;
    int o = idx & 127, kc = idx >> 7;
    int k = kc >> 8, c = kc & 255;
    g_wdefT[idx] = w_dcn[((size_t)o * CIN + c) * 9 + k];
}

__global__ void k_prep_wupT(const float* __restrict__ w_up) {
    int idx = blockIdx.x * 256 + threadIdx.x;
    if (idx >= 4 * 512 * 128) return;
    int o = idx & 127;
    int kcpar = idx >> 7;
    int kc = kcpar & 511, par = kcpar >> 9;
    int i  = kc >> 2, dh = (kc >> 1) & 1, dw = kc & 1;
    int py = par >> 1, px = par & 1;
    int kh = 3 - (py + 2 * dh);
    int kw = 3 - (px + 2 * dw);
    g_wupT[idx] = w_up[(((size_t)i * 128 + o) * 4 + kh) * 4 + kw];
}

// ---------------- K2: bilinear sampling into samp[b][k][c][p] -----------
__global__ __launch_bounds__(256) void k_sample(const float* __restrict__ x) {
    const int k     = blockIdx.x;   // 0..8
    const int b     = blockIdx.y;   // 0..15
    const int chalf = blockIdx.z;   // 0..1 (128 channels each)
    const int t = threadIdx.x;

    __shared__ int   s_idx[4][1024];
    __shared__ float s_w[4][1024];

    const float* offb = g_off + (size_t)b * 27 * 1024;
    const int ky = k / 3 - 1, kx = k % 3 - 1;

    for (int p = t; p < 1024; p += 256) {
        float dy = offb[(size_t)(2 * k) * 1024 + p];
        float dx = offb[(size_t)(2 * k + 1) * 1024 + p];
        float m  = offb[(size_t)(18 + k) * 1024 + p];
        int h = p >> 5, w = p & 31;
        float pyf = (float)(h + ky) + dy;
        float pxf = (float)(w + kx) + dx;
        float y0f = floorf(pyf), x0f = floorf(pxf);
        float wy = pyf - y0f, wx = pxf - x0f;
        int y0 = (int)y0f, x0 = (int)x0f;
#pragma unroll
        for (int slot = 0; slot < 4; slot++) {
            int dyc = slot >> 1, dxc = slot & 1;
            int yc = y0 + dyc, xc = x0 + dxc;
            bool valid = (yc >= 0) && (yc <= HH - 1) && (xc >= 0) && (xc <= WW - 1);
            int yi = min(HH - 1, max(0, yc));
            int xi = min(WW - 1, max(0, xc));
            float wgt = (dyc ? wy : 1.f - wy) * (dxc ? wx : 1.f - wx);
            s_idx[slot][p] = yi * WW + xi;
            s_w[slot][p]   = valid ? wgt * m : 0.f;
        }
    }
    __syncthreads();

    const float* xb = x + ((size_t)b * CIN + chalf * 128) * 1024;
    float* Sb = g_samp + (((size_t)(b * 9 + k) * CIN) + chalf * 128) * 1024;

    for (int p = t; p < 1024; p += 256) {
        int   i0 = s_idx[0][p], i1 = s_idx[1][p], i2 = s_idx[2][p], i3 = s_idx[3][p];
        float w0 = s_w[0][p],   w1 = s_w[1][p],   w2 = s_w[2][p],   w3 = s_w[3][p];
        const float* xp = xb;
        float* sp = Sb + p;
#pragma unroll 4
        for (int c = 0; c < 128; c++) {
            float v = w0 * __ldg(xp + i0) + w1 * __ldg(xp + i1) +
                      w2 * __ldg(xp + i2) + w3 * __ldg(xp + i3);
            sp[(size_t)c << 10] = v;
            xp += 1024;
        }
    }
}

// ---------------- K3: deform GEMM  (M=128, N=1024/b, K=2304) ------------
// out[b,o,p] = sum_kc g_wdefT[kc][o] * g_samp[b][kc][p] + bias[o]
__global__ __launch_bounds__(256) void k_gemm_deform(const float* __restrict__ bias) {
    const int pt = blockIdx.x;   // 0..7 (128 cols each)
    const int b  = blockIdx.y;   // 0..15
    const int bid = blockIdx.y * 8 + blockIdx.x;

    __shared__ float As[8 * 128];
    __shared__ float Bs[8 * 128];
    __shared__ float Red[16 * 128];

    const int t  = threadIdx.x;
    const int tx = t & 15, ty = t >> 4;

    float acc[8][8];
#pragma unroll
    for (int i = 0; i < 8; i++)
#pragma unroll
        for (int j = 0; j < 8; j++) acc[i][j] = 0.f;

    const float* Sb = g_samp + (size_t)b * KDEF * 1024 + pt * 128;
    const float4* Ag = reinterpret_cast<const float4*>(g_wdefT);

    const int r  = t >> 5;
    const int c4 = (t & 31) << 2;

    for (int kc0 = 0; kc0 < KDEF; kc0 += 8) {
        reinterpret_cast<float4*>(As)[t] = Ag[kc0 * 32 + t];
        *reinterpret_cast<float4*>(&Bs[r * 128 + c4]) =
            *reinterpret_cast<const float4*>(Sb + (size_t)(kc0 + r) * 1024 + c4);
        __syncthreads();
#pragma unroll
        for (int kk = 0; kk < 8; kk++) {
            float a[8], bb[8];
            *(float4*)&a[0]  = *(float4*)&As[kk * 128 + ty * 8];
            *(float4*)&a[4]  = *(float4*)&As[kk * 128 + ty * 8 + 4];
            *(float4*)&bb[0] = *(float4*)&Bs[kk * 128 + tx * 8];
            *(float4*)&bb[4] = *(float4*)&Bs[kk * 128 + tx * 8 + 4];
#pragma unroll
            for (int i = 0; i < 8; i++)
#pragma unroll
                for (int j = 0; j < 8; j++)
                    acc[i][j] = fmaf(a[i], bb[j], acc[i][j]);
        }
        __syncthreads();
    }

    // epilogue: bias, write, BN partial sums (deterministic)
    float* Y = g_y + ((size_t)b * COUT) * 1024 + pt * 128;
    float rs[8], rq[8];
#pragma unroll
    for (int i = 0; i < 8; i++) {
        int o = ty * 8 + i;
        float bi = __ldg(bias + o);
        float s = 0.f, q = 0.f;
#pragma unroll
        for (int j = 0; j < 8; j++) {
            float v = acc[i][j] + bi;
            acc[i][j] = v;
            s += v; q += v * v;
        }
        rs[i] = s; rq[i] = q;
        *(float4*)(Y + (size_t)o * 1024 + tx * 8)     = *(float4*)&acc[i][0];
        *(float4*)(Y + (size_t)o * 1024 + tx * 8 + 4) = *(float4*)&acc[i][4];
    }
#pragma unroll
    for (int i = 0; i < 8; i++) Red[tx * 128 + ty * 8 + i] = rs[i];
    __syncthreads();
    if (t < 128) {
        float s = 0.f;
#pragma unroll
        for (int xq = 0; xq < 16; xq++) s += Red[xq * 128 + t];
        g_part1[((size_t)bid * 128 + t) * 2 + 0] = s;
    }
    __syncthreads();
#pragma unroll
    for (int i = 0; i < 8; i++) Red[tx * 128 + ty * 8 + i] = rq[i];
    __syncthreads();
    if (t < 128) {
        float q = 0.f;
#pragma unroll
        for (int xq = 0; xq < 16; xq++) q += Red[xq * 128 + t];
        g_part1[((size_t)bid * 128 + t) * 2 + 1] = q;
    }
}

// ---------------- BN1 finalize + normalize ----------------
__global__ void k_bn1(const float* __restrict__ g1, const float* __restrict__ bt1) {
    int o = threadIdx.x;  // 128
    float s = 0.f, q = 0.f;
    for (int blk = 0; blk < 128; blk++) {
        s += g_part1[((size_t)blk * 128 + o) * 2 + 0];
        q += g_part1[((size_t)blk * 128 + o) * 2 + 1];
    }
    float mean = s / (float)N1TOT;
    float var  = q / (float)N1TOT - mean * mean;
    float sc = g1[o] * rsqrtf(var + 1e-5f);
    g_scale1[o] = sc;
    g_shift1[o] = bt1[o] - mean * sc;
}

__global__ void k_norm1() {
    int f = blockIdx.x * 256 + threadIdx.x;  // float4 id, 524288 total
    int e = f << 2;
    int o = (e >> 10) & 127;
    float sc = g_scale1[o], sh = g_shift1[o];
    float4 v = reinterpret_cast<const float4*>(g_y)[f];
    v.x = fmaxf(0.f, v.x * sc + sh);
    v.y = fmaxf(0.f, v.y * sc + sh);
    v.z = fmaxf(0.f, v.z * sc + sh);
    v.w = fmaxf(0.f, v.w * sc + sh);
    reinterpret_cast<float4*>(g_y2)[f] = v;
}

// ---------------- K6: transposed conv as 4 parity 2x2 convs (GEMM) ------
// z[b,par,o,p] = sum_{i,dh,dw} Wsub[par][(i,dh,dw)][o] * y2[b,i,iy,ix]
__global__ __launch_bounds__(256) void k_deconv() {
    const int pt  = blockIdx.x;   // 0..7  (4 a-rows x 32 c-cols each)
    const int par = blockIdx.y;   // 0..3
    const int b   = blockIdx.z;   // 0..15
    const int py = par >> 1, px = par & 1;
    const int a0 = pt * 4;
    const int bid = (blockIdx.z * 4 + blockIdx.y) * 8 + blockIdx.x;  // 0..511

    __shared__ float As[8 * 128];
    __shared__ float Bs[8 * 128];
    __shared__ float Red[16 * 128];

    const int t  = threadIdx.x;
    const int tx = t & 15, ty = t >> 4;

    float acc[8][8];
#pragma unroll
    for (int i = 0; i < 8; i++)
#pragma unroll
        for (int j = 0; j < 8; j++) acc[i][j] = 0.f;

    const float4* Ag = reinterpret_cast<const float4*>(g_wupT + (size_t)par * KUP * 128);
    const float* Yb = g_y2 + (size_t)b * COUT * 1024;

    const int kkld = t >> 5;
    const int n0   = (t & 31) << 2;

    for (int kc0 = 0; kc0 < KUP; kc0 += 8) {
        reinterpret_cast<float4*>(As)[t] = Ag[kc0 * 32 + t];
        {
            int kc = kc0 + kkld;
            int i  = kc >> 2, dh = (kc >> 1) & 1, dw = kc & 1;
            const float* Yp = Yb + (size_t)i * 1024;
#pragma unroll
            for (int jj = 0; jj < 4; jj++) {
                int n = n0 + jj;
                int arow = n >> 5, c = n & 31;
                int iy = a0 + arow + py + dh - 1;
                int ix = c + px + dw - 1;
                float v = 0.f;
                if (iy >= 0 && iy < HH && ix >= 0 && ix < WW)
                    v = __ldg(Yp + iy * WW + ix);
                Bs[kkld * 128 + n] = v;
            }
        }
        __syncthreads();
#pragma unroll
        for (int kk = 0; kk < 8; kk++) {
            float a[8], bb[8];
            *(float4*)&a[0]  = *(float4*)&As[kk * 128 + ty * 8];
            *(float4*)&a[4]  = *(float4*)&As[kk * 128 + ty * 8 + 4];
            *(float4*)&bb[0] = *(float4*)&Bs[kk * 128 + tx * 8];
            *(float4*)&bb[4] = *(float4*)&Bs[kk * 128 + tx * 8 + 4];
#pragma unroll
            for (int i = 0; i < 8; i++)
#pragma unroll
                for (int j = 0; j < 8; j++)
                    acc[i][j] = fmaf(a[i], bb[j], acc[i][j]);
        }
        __syncthreads();
    }

    float* Z = g_z + ((size_t)(b * 4 + par) * COUT) * 1024 + pt * 128;
    float rs[8], rq[8];
#pragma unroll
    for (int i = 0; i < 8; i++) {
        int o = ty * 8 + i;
        float s = 0.f, q = 0.f;
#pragma unroll
        for (int j = 0; j < 8; j++) { float v = acc[i][j]; s += v; q += v * v; }
        rs[i] = s; rq[i] = q;
        *(float4*)(Z + (size_t)o * 1024 + tx * 8)     = *(float4*)&acc[i][0];
        *(float4*)(Z + (size_t)o * 1024 + tx * 8 + 4) = *(float4*)&acc[i][4];
    }
#pragma unroll
    for (int i = 0; i < 8; i++) Red[tx * 128 + ty * 8 + i] = rs[i];
    __syncthreads();
    if (t < 128) {
        float s = 0.f;
#pragma unroll
        for (int xq = 0; xq < 16; xq++) s += Red[xq * 128 + t];
        g_part2[((size_t)bid * 128 + t) * 2 + 0] = s;
    }
    __syncthreads();
#pragma unroll
    for (int i = 0; i < 8; i++) Red[tx * 128 + ty * 8 + i] = rq[i];
    __syncthreads();
    if (t < 128) {
        float q = 0.f;
#pragma unroll
        for (int xq = 0; xq < 16; xq++) q += Red[xq * 128 + t];
        g_part2[((size_t)bid * 128 + t) * 2 + 1] = q;
    }
}

// ---------------- BN2 finalize + final output (parity de-interleave) ----
__global__ void k_bn2(const float* __restrict__ g2, const float* __restrict__ bt2) {
    int o = threadIdx.x;  // 128
    float s = 0.f, q = 0.f;
    for (int blk = 0; blk < 512; blk++) {
        s += g_part2[((size_t)blk * 128 + o) * 2 + 0];
        q += g_part2[((size_t)blk * 128 + o) * 2 + 1];
    }
    float mean = s / (float)N2TOT;
    float var  = q / (float)N2TOT - mean * mean;
    float sc = g2[o] * rsqrtf(var + 1e-5f);
    g_scale2[o] = sc;
    g_shift2[o] = bt2[o] - mean * sc;
}

__global__ void k_out(float* __restrict__ out) {
    int f = blockIdx.x * 256 + threadIdx.x;  // float4 id, 2097152 total
    int e = f << 2;
    int b   = e >> 19;            // 128*64*64 = 524288 per batch
    int o   = (e >> 12) & 127;
    int oy  = (e >> 6) & 63;
    int ox0 = e & 63;
    float sc = g_scale2[o], sh = g_shift2[o];
    int a = oy >> 1;
    int pybit = oy & 1;
    float r[4];
#pragma unroll
    for (int j = 0; j < 4; j++) {
        int ox = ox0 + j;
        int par = pybit * 2 + (ox & 1);
        int c = ox >> 1;
        float z = g_z[((size_t)(b * 4 + par) * COUT + o) * 1024 + a * 32 + c];
        r[j] = fmaxf(0.f, z * sc + sh);
    }
    reinterpret_cast<float4*>(out)[f] = *(float4*)r;
}

// ---------------- launcher ----------------
extern "C" void kernel_launch(void* const* d_in, const int* in_sizes, int n_in,
                              void* d_out, int out_size) {
    const float* x     = (const float*)d_in[0];
    const float* w_off = (const float*)d_in[1];
    const float* b_off = (const float*)d_in[2];
    const float* w_dcn = (const float*)d_in[3];
    const float* b_dcn = (const float*)d_in[4];
    const float* g1    = (const float*)d_in[5];
    const float* bt1   = (const float*)d_in[6];
    const float* w_up  = (const float*)d_in[7];
    const float* g2    = (const float*)d_in[8];
    const float* bt2   = (const float*)d_in[9];
    float* out = (float*)d_out;

    // 1) offset conv + reduce (+ sigmoid on mask channels)
    k_offconv<<<dim3(4, 16, 4), 256>>>(x, w_off);
    k_offred<<<1728, 256>>>(b_off);

    // weight prepacks (independent; same stream keeps ordering simple)
    k_prep_wdefT<<<1152, 256>>>(w_dcn);
    k_prep_wupT<<<1024, 256>>>(w_up);

    // 2) bilinear sampling
    k_sample<<<dim3(9, 16, 2), 256>>>(x);

    // 3) deform GEMM + BN1 partials
    k_gemm_deform<<<dim3(8, 16), 256>>>(b_dcn);
    k_bn1<<<1, 128>>>(g1, bt1);
    k_norm1<<<2048, 256>>>();

    // 4) transposed conv (4 parity sub-convs) + BN2 partials
    k_deconv<<<dim3(8, 4, 16), 256>>>();
    k_bn2<<<1, 128>>>(g2, bt2);

    // 5) BN2 normalize + parity de-interleave into final NCHW output
    k_out<<<8192, 256>>>(out);
}